// round 4
// baseline (speedup 1.0000x reference)
#include <cuda_runtime.h>
#include <cuda_bf16.h>
#include <cstdint>

#define Cc 256
#define Ss 1024
#define Nn 32768
#define Dd 256
#define Kk 1024
#define DE 768            // split-extended reduction depth (hi|lo|hi vs hi|hi|lo)
#define OUT_LOSS 8388608
#define OUT_ENC  8388610

typedef unsigned long long u64;
typedef unsigned int u32;

// ---------------- device scratch (no allocations allowed) -------------------
__device__ __align__(16) __nv_bfloat16 gA[Nn * DE];   // tokens: [hi(256)|lo(256)|hi(256)]
__device__ __align__(16) __nv_bfloat16 gB[Kk * DE];   // codes:  [hi(256)|hi(256)|lo(256)]
__device__ float g_wnorm[Kk];
__device__ float g_xnorm[Nn];
__device__ float g_dmin[Nn];
__device__ int   g_idx[Nn];
__device__ int   g_cnt[Kk];
__device__ int   g_list[Nn];
__device__ int   g_nres;

// ---------------- helpers ----------------------------------------------------
__device__ __forceinline__ u32 smem_u32(const void* p){
  u32 a; asm("{ .reg .u64 t; cvta.to.shared.u64 t, %1; cvt.u32.u64 %0, t; }" : "=r"(a) : "l"(p));
  return a;
}
#define CP_ASYNC16(d, g) asm volatile("cp.async.cg.shared.global [%0], [%1], 16;" :: "r"(d), "l"(g))
#define CP_COMMIT()  asm volatile("cp.async.commit_group;" ::: "memory")
#define CP_WAIT1()   asm volatile("cp.async.wait_group 1;" ::: "memory")
#define CP_WAIT0()   asm volatile("cp.async.wait_group 0;" ::: "memory")

__device__ __forceinline__ void ldsm4(u32& a0, u32& a1, u32& a2, u32& a3, u32 addr){
  asm volatile("ldmatrix.sync.aligned.m8n8.x4.shared.b16 {%0,%1,%2,%3}, [%4];"
    : "=r"(a0), "=r"(a1), "=r"(a2), "=r"(a3) : "r"(addr));
}
__device__ __forceinline__ void mma16816(float* c, const u32* a, const u32* b){
  asm volatile("mma.sync.aligned.m16n8k16.row.col.f32.bf16.bf16.f32 "
    "{%0,%1,%2,%3}, {%4,%5,%6,%7}, {%8,%9}, {%0,%1,%2,%3};"
    : "+f"(c[0]), "+f"(c[1]), "+f"(c[2]), "+f"(c[3])
    : "r"(a[0]), "r"(a[1]), "r"(a[2]), "r"(a[3]), "r"(b[0]), "r"(b[1]));
}

__device__ __forceinline__ u32 ford(float v){
  u32 u = __float_as_uint(v);
  return (u & 0x80000000u) ? ~u : (u | 0x80000000u);
}
__device__ __forceinline__ float funord(u32 u){
  return __uint_as_float((u & 0x80000000u) ? (u & 0x7fffffffu) : ~u);
}

// ---------------- small kernels ---------------------------------------------
__global__ void vq_init(){
  g_cnt[threadIdx.x] = 0;
  if (threadIdx.x == 0) g_nres = 0;
}

__global__ void vq_wnorm(const float* __restrict__ W){
  int r = blockIdx.x * 8 + (threadIdx.x >> 5);
  int lane = threadIdx.x & 31;
  const float4* w4 = (const float4*)(W + r * Dd);
  float4 a = w4[lane], b = w4[lane + 32];
  float s = a.x*a.x + a.y*a.y + a.z*a.z + a.w*a.w
          + b.x*b.x + b.y*b.y + b.z*b.z + b.w*b.w;
  #pragma unroll
  for (int o = 16; o > 0; o >>= 1) s += __shfl_xor_sync(0xffffffffu, s, o);
  if (lane == 0) g_wnorm[r] = s;
}

// B' = [whi | whi | wlo] per code row
__global__ void vq_wsplit(const float* __restrict__ W){
  int g = blockIdx.x * 256 + threadIdx.x;      // 98304 threads
  int row = g / 96, cb = g % 96;
  int seg = cb >> 5;                           // 0,1 -> hi ; 2 -> lo
  int c0 = (cb & 31) * 8;
  const float* src = W + row * Dd + c0;
  __nv_bfloat16 o[8];
  #pragma unroll
  for (int e = 0; e < 8; e++){
    float v = src[e];
    __nv_bfloat16 h = __float2bfloat16(v);
    o[e] = (seg == 2) ? __float2bfloat16(v - __bfloat162float(h)) : h;
  }
  *(uint4*)(gB + row * DE + cb * 8) = *(uint4*)o;
}

// A' = [xhi | xlo | xhi] per token row + exact xnorm. BCHW transpose via smem.
__global__ __launch_bounds__(256) void vq_prep(const float* __restrict__ X){
  __shared__ float tile[Dd][33];
  __shared__ float pxn[8][32];
  int t = threadIdx.x, w = t >> 5, l = t & 31;
  int b = blockIdx.x >> 5, s0 = (blockIdx.x & 31) << 5;
  const float* Xp = X + b * (Dd * Ss) + s0 + l;
  float acc = 0.f;
  #pragma unroll
  for (int i = 0; i < 32; i++){
    int c = w + i * 8;
    float v = Xp[c * Ss];
    tile[c][l] = v; acc += v * v;
  }
  pxn[w][l] = acc;
  __syncthreads();
  if (t < 32){
    float s = 0.f;
    #pragma unroll
    for (int w2 = 0; w2 < 8; w2++) s += pxn[w2][t];
    g_xnorm[b * Ss + s0 + t] = s;
  }
  int tr = t >> 3, lane8 = t & 7;
  __nv_bfloat16* dst = gA + (size_t)(b * Ss + s0 + tr) * DE;
  #pragma unroll
  for (int i = 0; i < 12; i++){
    int cb = lane8 + i * 8;                    // 0..95
    int seg = cb >> 5;                         // 0 hi, 1 lo, 2 hi
    int c0 = (cb & 31) * 8;
    __nv_bfloat16 o[8];
    #pragma unroll
    for (int e = 0; e < 8; e++){
      float v = tile[c0 + e][tr];
      __nv_bfloat16 h = __float2bfloat16(v);
      o[e] = (seg == 1) ? __float2bfloat16(v - __bfloat162float(h)) : h;
    }
    *(uint4*)(dst + cb * 8) = *(uint4*)o;
  }
}

// ---------------- warp-MMA GEMM + fused top-2 argmin ------------------------
// dyn smem: A resident [128 tok][96 x 16B] = 196608B at 0 (XOR-swizzled 16B chunks),
//           B double buffer 2 x [128 codes][8 x 16B] = 32768B after A.
#define A_BYTES 196608
#define B_BYTES 16384
#define SMEM_TOT (A_BYTES + 2*B_BYTES)

__device__ __forceinline__ void fillA(u32 ab, int n0, int t){
  const char* src = (const char*)gA + (size_t)n0 * (DE * 2);
  #pragma unroll
  for (int j = 0; j < 48; j++){
    int idx = t + j * 256;
    int row = idx / 96, c = idx % 96;
    u32 dst = ab + (u32)(row * 1536) + (u32)((c ^ (row & 7)) << 4);
    CP_ASYNC16(dst, src + (size_t)row * 1536 + c * 16);
  }
}
__device__ __forceinline__ void fillB(u32 bb, int nc, int kc, int t){
  const char* src = (const char*)gB + (size_t)(nc * 128) * 1536 + (size_t)kc * 128;
  #pragma unroll
  for (int j = 0; j < 4; j++){
    int idx = t + j * 256;
    int n = idx >> 3, c = idx & 7;
    u32 dst = bb + (u32)(n * 128) + (u32)((c ^ (n & 7)) << 4);
    CP_ASYNC16(dst, src + (size_t)n * 1536 + c * 16);
  }
}

__global__ __launch_bounds__(256, 1) void vq_gemm_tc(){
  extern __shared__ __align__(16) char dsm[];
  const u32 dbase = smem_u32(dsm);
  const int t = threadIdx.x, lane = t & 31, w = t >> 5;
  const int wm = w & 1, wn = w >> 1;
  const int n0 = blockIdx.x * 128;

  // fragment source rows
  const int arow = wm * 64 + (lane & 15);                       // + mt*16
  const int bn   = wn * 32 + ((lane >> 4) << 3) + (lane & 7);   // + ntp*16

  float t1[8], t2[8]; int ti[8];
  #pragma unroll
  for (int i = 0; i < 8; i++){ t1[i] = 3.4e38f; t2[i] = 3.4e38f; ti[i] = 0; }

  fillA(dbase, n0, t);
  fillB(dbase + A_BYTES, 0, 0, t);
  CP_COMMIT();

  float acc[4][4][4];
  for (int nc = 0; nc < 8; nc++){
    #pragma unroll
    for (int mt = 0; mt < 4; mt++)
      #pragma unroll
      for (int nt = 0; nt < 4; nt++)
        #pragma unroll
        for (int q = 0; q < 4; q++) acc[mt][nt][q] = 0.f;

    for (int kc = 0; kc < 12; kc++){
      const int g = nc * 12 + kc;
      const int buf = g & 1;
      if (g + 1 < 96){
        int nn = (kc == 11) ? nc + 1 : nc;
        int nk = (kc == 11) ? 0 : kc + 1;
        fillB(dbase + A_BYTES + (u32)((buf ^ 1) * B_BYTES), nn, nk, t);
        CP_COMMIT();
        CP_WAIT1();
      } else {
        CP_WAIT0();
      }
      __syncthreads();

      const u32 bb = dbase + A_BYTES + (u32)(buf * B_BYTES);
      #pragma unroll
      for (int ks = 0; ks < 4; ks++){
        u32 afr[4][4];
        int ca = kc * 8 + ks * 2 + (lane >> 4);
        #pragma unroll
        for (int mt = 0; mt < 4; mt++){
          int r = arow + mt * 16;
          u32 ad = dbase + (u32)(r * 1536) + (u32)((ca ^ (r & 7)) << 4);
          ldsm4(afr[mt][0], afr[mt][1], afr[mt][2], afr[mt][3], ad);
        }
        u32 bfr[4][2];
        int ckl = ks * 2 + ((lane >> 3) & 1);
        #pragma unroll
        for (int ntp = 0; ntp < 2; ntp++){
          int n = bn + ntp * 16;
          u32 bd = bb + (u32)(n * 128) + (u32)((ckl ^ (n & 7)) << 4);
          ldsm4(bfr[2*ntp][0], bfr[2*ntp][1], bfr[2*ntp+1][0], bfr[2*ntp+1][1], bd);
        }
        #pragma unroll
        for (int mt = 0; mt < 4; mt++)
          #pragma unroll
          for (int nt = 0; nt < 4; nt++)
            mma16816(acc[mt][nt], afr[mt], bfr[nt]);
      }

      if (kc == 11){
        // distances + per-thread top2, ascending code order for tie-break
        int cb0 = nc * 128 + wn * 32 + (lane & 3) * 2;
        #pragma unroll
        for (int nt = 0; nt < 4; nt++){
          int c0 = cb0 + nt * 8;
          float w0 = g_wnorm[c0], w1 = g_wnorm[c0 + 1];
          #pragma unroll
          for (int mt = 0; mt < 4; mt++)
            #pragma unroll
            for (int h = 0; h < 2; h++){
              int s = mt * 2 + h;
              float d0 = fmaf(-2.0f, acc[mt][nt][h*2+0], w0);
              float d1 = fmaf(-2.0f, acc[mt][nt][h*2+1], w1);
              if (d0 < t1[s]){ t2[s] = t1[s]; t1[s] = d0; ti[s] = c0; }
              else if (d0 < t2[s]) t2[s] = d0;
              if (d1 < t1[s]){ t2[s] = t1[s]; t1[s] = d1; ti[s] = c0 + 1; }
              else if (d1 < t2[s]) t2[s] = d1;
            }
        }
      }
      __syncthreads();
    }
  }

  // warp-level merge across the 4 lanes sharing each token row
  u64 key[8];
  #pragma unroll
  for (int s = 0; s < 8; s++) key[s] = ((u64)ford(t1[s]) << 32) | (u32)ti[s];
  #pragma unroll
  for (int off = 1; off <= 2; off <<= 1){
    #pragma unroll
    for (int s = 0; s < 8; s++){
      u64 ko  = __shfl_xor_sync(0xffffffffu, key[s], off);
      float mo = __shfl_xor_sync(0xffffffffu, t2[s], off);
      float va = funord((u32)(key[s] >> 32));
      float vb = funord((u32)(ko >> 32));
      t2[s] = fminf(fminf(t2[s], mo), fmaxf(va, vb));
      if (ko < key[s]) key[s] = ko;
    }
  }
  // overlay scratch on B region (done with B buffers)
  u64*  wm1 = (u64*)(dsm + A_BYTES);
  float* wm2 = (float*)(dsm + A_BYTES + 4096);
  if ((lane & 3) == 0){
    #pragma unroll
    for (int s = 0; s < 8; s++){
      int mt = s >> 1, h = s & 1;
      int row = wm * 64 + mt * 16 + (lane >> 2) + h * 8;
      wm1[wn * 128 + row] = key[s];
      wm2[wn * 128 + row] = t2[s];
    }
  }
  __syncthreads();
  if (t < 128){
    u64 bk = wm1[t]; float m2 = wm2[t];
    #pragma unroll
    for (int q = 1; q < 4; q++){
      u64 k2 = wm1[q * 128 + t]; float mm = wm2[q * 128 + t];
      float va = funord((u32)(bk >> 32));
      float vb = funord((u32)(k2 >> 32));
      m2 = fminf(fminf(m2, mm), fmaxf(va, vb));
      if (k2 < bk) bk = k2;
    }
    int tok = n0 + t;
    float d1 = funord((u32)(bk >> 32));
    g_idx[tok]  = (int)(bk & 0xffffffffu);
    g_dmin[tok] = g_xnorm[tok] + d1;
    if (m2 - d1 < 0.05f){
      int p = atomicAdd(&g_nres, 1);
      g_list[p] = tok;
    }
  }
}

// exact fp32 re-solve for near-tie tokens
__global__ __launch_bounds__(256) void vq_rescue(const float* __restrict__ X,
                                                 const float* __restrict__ W){
  __shared__ float xt[Dd];
  __shared__ u64 red;
  int t = threadIdx.x;
  int nr = g_nres;
  for (int r = blockIdx.x; r < nr; r += 32){
    int tok = g_list[r];
    int b = tok >> 10, s = tok & 1023;
    xt[t] = X[b * (Dd * Ss) + t * Ss + s];
    if (t == 0) red = 0xFFFFFFFFFFFFFFFFull;
    __syncthreads();
    u64 best = 0xFFFFFFFFFFFFFFFFull;
    #pragma unroll 1
    for (int q = 0; q < 4; q++){
      int k = t * 4 + q;
      const float* wr = W + k * Dd;
      float s0 = 0, s1 = 0, s2 = 0, s3 = 0;
      #pragma unroll 8
      for (int d = 0; d < Dd; d += 4){
        s0 += xt[d] * wr[d];     s1 += xt[d+1] * wr[d+1];
        s2 += xt[d+2] * wr[d+2]; s3 += xt[d+3] * wr[d+3];
      }
      float dot = (s0 + s1) + (s2 + s3);
      float dist = g_wnorm[k] - 2.0f * dot;
      u64 kkey = ((u64)ford(dist) << 32) | (u32)k;
      if (kkey < best) best = kkey;
    }
    atomicMin(&red, best);
    __syncthreads();
    if (t == 0){
      u64 kkey = red;
      g_idx[tok]  = (int)(kkey & 0xffffffffu);
      g_dmin[tok] = g_xnorm[tok] + funord((u32)(kkey >> 32));
    }
    __syncthreads();
  }
}

__global__ void vq_cnt(){
  int g = blockIdx.x * 256 + threadIdx.x;
  atomicAdd(&g_cnt[g_idx[g]], 1);
}

// quantized output in BCHW
__global__ void vq_gather(const float* __restrict__ W, float* __restrict__ out){
  int g   = blockIdx.x * 256 + threadIdx.x;
  int c4  = g >> 15;
  int rem = g & 32767;
  int b = rem >> 10, s = rem & 1023;
  int id = g_idx[rem];
  float4 w = *(const float4*)(W + id * Dd + c4 * 4);
  float* o = out + b * (Cc * Ss) + (c4 * 4) * Ss + s;
  o[0] = w.x; o[Ss] = w.y; o[2*Ss] = w.z; o[3*Ss] = w.w;
}

__global__ void vq_enc(float* __restrict__ enc){
  int g  = blockIdx.x * 256 + threadIdx.x;
  int n  = g >> 9;
  int k2 = (g & 511) * 2;
  int id = g_idx[n];
  float2 v;
  v.x = (id == k2    ) ? 1.0f : 0.0f;
  v.y = (id == k2 + 1) ? 1.0f : 0.0f;
  *(float2*)(enc + (size_t)n * Kk + k2) = v;
}

__global__ void vq_final(float* __restrict__ scal){
  __shared__ float sh[1024];
  int t = threadIdx.x;
  float s = 0.0f;
  for (int i = t; i < Nn; i += 1024) s += g_dmin[i];
  sh[t] = s; __syncthreads();
  for (int o = 512; o > 0; o >>= 1){ if (t < o) sh[t] += sh[t + o]; __syncthreads(); }
  float losssum = sh[0];
  __syncthreads();
  float p = (float)g_cnt[t] * (1.0f / (float)Nn);
  sh[t] = -p * logf(p + 1e-10f);
  __syncthreads();
  for (int o = 512; o > 0; o >>= 1){ if (t < o) sh[t] += sh[t + o]; __syncthreads(); }
  if (t == 0){
    scal[0] = 0.25f * losssum / (float)(Nn * Dd);
    scal[1] = sh[0];
  }
}

// ---------------- launch -----------------------------------------------------
extern "C" void kernel_launch(void* const* d_in, const int* in_sizes, int n_in,
                              void* d_out, int out_size){
  (void)in_sizes; (void)n_in; (void)out_size;
  const float* X = (const float*)d_in[0];
  const float* W = (const float*)d_in[1];
  float* out = (float*)d_out;

  cudaFuncSetAttribute(vq_gemm_tc, cudaFuncAttributeMaxDynamicSharedMemorySize, SMEM_TOT);

  vq_init   <<<1, Kk>>>();
  vq_wnorm  <<<Kk / 8, 256>>>(W);
  vq_wsplit <<<384, 256>>>(W);
  vq_prep   <<<1024, 256>>>(X);
  vq_gemm_tc<<<256, 256, SMEM_TOT>>>();
  vq_rescue <<<32, 256>>>(X, W);
  vq_cnt    <<<Nn / 256, 256>>>();
  vq_gather <<<(Nn * Dd / 4) / 256, 256>>>(W, out);
  vq_enc    <<<(Nn * (Kk / 2)) / 256, 256>>>(out + OUT_ENC);
  vq_final  <<<1, Kk>>>(out + OUT_LOSS);
}